// round 5
// baseline (speedup 1.0000x reference)
#include <cuda_runtime.h>
#include <cuda_bf16.h>

// out[b,s,e] = W_e[e, tokens[b,s]] + W_p[s,e]
// tokens: (2,2048) int32, W_e: (1024,32000) f32, W_p: (2048,1024) f32
// out: (2,2048,1024) f32
//
// Inverted (streaming) formulation. The random column-gather of W_e fetches
// ~114MB of unique 64B granules out of 128MB total -- so instead of gathering
// (random-access BW ~4.4TB/s, measured R1-R4), stream ALL of W_e sequentially
// (~12% more bytes at ~1.5x the bandwidth):
//   - tile W_e into (32 e-rows x 250 v-cols) smem tiles (32KB static smem)
//   - grid = 32 e-groups x 128 v-bins, v-bin fast => concurrent wave reads a
//     dense contiguous swath of W_e at streaming bandwidth
//   - each block scans the token list (16KB, L2-broadcast) and, for tokens
//     whose v lands in its bin, emits out[tok][e0:e0+32] (128B contiguous
//     store) from a conflict-free smem column read + W_p add.
// Every output element is written exactly once (bins partition v-space).

#define B 2
#define S 2048
#define E 1024
#define V 32000
#define NTOK (B * S)          // 4096

#define E_TILE 32
#define V_TILE 250
#define NBINS (V / V_TILE)    // 128
#define NEG (E / E_TILE)      // 32
#define SSTRIDE (V_TILE + 1)  // 251; 251 mod 32 = 27 (coprime) -> conflict-free
                              // column reads across the 32 e-rows

__global__ __launch_bounds__(256)
void embedding_stream_kernel(const int* __restrict__ tokens,
                             const float* __restrict__ W_e,
                             const float* __restrict__ W_p,
                             float* __restrict__ out) {
    __shared__ float tile[E_TILE * SSTRIDE];   // 32KB + pad

    int bin = blockIdx.x & (NBINS - 1);        // v-bin: fast axis (dense sweep)
    int eg  = blockIdx.x >> 7;                 // e-group: slow axis
    int tid = threadIdx.x;

    int v0 = bin * V_TILE;
    int e0 = eg * E_TILE;

    // ---- Phase 1: stream the (32 x 250) W_e tile into smem.
    // float2 loads (segment byte offset is 8B-aligned for all bins).
    const float2* src = reinterpret_cast<const float2*>(W_e + (size_t)e0 * V + v0);
    // Row r of the tile lives at W_e + (e0+r)*V + v0; 125 float2 per row.
    for (int i = tid; i < E_TILE * (V_TILE / 2); i += 256) {
        int r = i / (V_TILE / 2);
        int c = i - r * (V_TILE / 2);
        float2 val = __ldg(reinterpret_cast<const float2*>(
            W_e + (size_t)(e0 + r) * V + v0) + c);
        tile[r * SSTRIDE + 2 * c]     = val.x;
        tile[r * SSTRIDE + 2 * c + 1] = val.y;
    }
    __syncthreads();

    // ---- Phase 2: scan tokens; for hits in this v-bin, emit 128B output row.
#pragma unroll 1
    for (int i = 0; i < NTOK / 256; i++) {
        int tk = tid + 256 * i;                // 0..4095 (coalesced scan)
        int v  = __ldg(&tokens[tk]);
        unsigned vl = (unsigned)(v - v0);
        if (vl < V_TILE) {
            int s = tk & (S - 1);
            const float4* wp = reinterpret_cast<const float4*>(
                W_p + (size_t)s * E + e0);
            float4* op = reinterpret_cast<float4*>(
                out + (size_t)tk * E + e0);
#pragma unroll
            for (int j = 0; j < E_TILE / 4; j++) {
                float4 p = __ldg(wp + j);
                float4 r;
                r.x = tile[(4 * j + 0) * SSTRIDE + vl] + p.x;
                r.y = tile[(4 * j + 1) * SSTRIDE + vl] + p.y;
                r.z = tile[(4 * j + 2) * SSTRIDE + vl] + p.z;
                r.w = tile[(4 * j + 3) * SSTRIDE + vl] + p.w;
                __stcs(op + j, r);             // streaming: out has no reuse
            }
        }
    }
}

extern "C" void kernel_launch(void* const* d_in, const int* in_sizes, int n_in,
                              void* d_out, int out_size) {
    const int*   tokens = (const int*)d_in[0];
    const float* W_e    = (const float*)d_in[1];
    const float* W_p    = (const float*)d_in[2];
    float*       out    = (float*)d_out;

    embedding_stream_kernel<<<NEG * NBINS, 256>>>(tokens, W_e, W_p, out);
}

// round 6
// speedup vs baseline: 1.5159x; 1.5159x over previous
#include <cuda_runtime.h>
#include <cuda_bf16.h>

// out[b,s,e] = W_e[e, tokens[b,s]] + W_p[s,e]
// tokens: (2,2048) int32, W_e: (1024,32000) f32, W_p: (2048,1024) f32
// out: (2,2048,1024) f32
//
// Streaming formulation, round 2. R5 showed the memory plan (stream all of
// W_e sequentially, ~152MB total at streaming BW) was hidden behind a
// 16.8M-iteration token scan (issue 43%, ALU 35%). Fix: bin the 4096 tokens
// by v-range ONCE per call (two tiny kernels, static __device__ scratch),
// so each stream block only visits its own ~32 hits.

#define B 2
#define S 2048
#define E 1024
#define V 32000
#define NTOK (B * S)          // 4096

#define E_TILE 32
#define V_TILE 250
#define NBINS (V / V_TILE)    // 128
#define NEG (E / E_TILE)      // 32
#define SSTRIDE (V_TILE + 1)  // 251 (mod 32 = 27, coprime -> conflict-free cols)

// Static scratch: bin counters + per-bin token lists (worst case: all tokens
// in one bin). No device allocation anywhere.
__device__ int g_bin_count[NBINS];
__device__ int g_bin_list[NBINS * NTOK];

__global__ void zero_kernel() {
    g_bin_count[threadIdx.x] = 0;
}

__global__ void bin_kernel(const int* __restrict__ tokens) {
    int tk = blockIdx.x * 256 + threadIdx.x;      // 0..4095
    int v  = __ldg(&tokens[tk]);
    int bin = v / V_TILE;
    int pos = atomicAdd(&g_bin_count[bin], 1);
    g_bin_list[bin * NTOK + pos] = tk;
}

__global__ __launch_bounds__(256)
void embedding_stream_kernel(const int* __restrict__ tokens,
                             const float* __restrict__ W_e,
                             const float* __restrict__ W_p,
                             float* __restrict__ out) {
    __shared__ float tile[E_TILE * SSTRIDE];      // ~32KB

    int bin = blockIdx.x & (NBINS - 1);           // v-bin: fast axis (dense sweep)
    int eg  = blockIdx.x >> 7;                    // e-group: slow axis
    int tid = threadIdx.x;

    int v0 = bin * V_TILE;
    int e0 = eg * E_TILE;

    // ---- Phase 1: stream the (32 x 250) W_e tile into smem (float2,
    //      8B-aligned for every bin since 250*4 = 1000 is a multiple of 8).
    for (int i = tid; i < E_TILE * (V_TILE / 2); i += 256) {
        int r = i / (V_TILE / 2);
        int c = i - r * (V_TILE / 2);
        float2 val = __ldg(reinterpret_cast<const float2*>(
            W_e + (size_t)(e0 + r) * V + v0) + c);
        tile[r * SSTRIDE + 2 * c]     = val.x;
        tile[r * SSTRIDE + 2 * c + 1] = val.y;
    }
    __syncthreads();

    // ---- Phase 2: only this bin's tokens. 8 threads cooperate per token
    //      (8 float4 = one 128B output row).
    int cnt = g_bin_count[bin];
    int j   = tid & 7;                            // float4 slot within row
    for (int h = tid >> 3; h < cnt; h += 32) {    // 32 tokens per pass
        int tk = g_bin_list[bin * NTOK + h];
        int vl = __ldg(&tokens[tk]) - v0;         // L2 hit (16KB, hot)
        int s  = tk & (S - 1);

        float4 p = __ldg(reinterpret_cast<const float4*>(
            W_p + (size_t)s * E + e0) + j);
        float4 r;
        r.x = tile[(4 * j + 0) * SSTRIDE + vl] + p.x;
        r.y = tile[(4 * j + 1) * SSTRIDE + vl] + p.y;
        r.z = tile[(4 * j + 2) * SSTRIDE + vl] + p.z;
        r.w = tile[(4 * j + 3) * SSTRIDE + vl] + p.w;
        __stcs(reinterpret_cast<float4*>(out + (size_t)tk * E + e0) + j, r);
    }
}

extern "C" void kernel_launch(void* const* d_in, const int* in_sizes, int n_in,
                              void* d_out, int out_size) {
    const int*   tokens = (const int*)d_in[0];
    const float* W_e    = (const float*)d_in[1];
    const float* W_p    = (const float*)d_in[2];
    float*       out    = (float*)d_out;

    zero_kernel<<<1, NBINS>>>();
    bin_kernel<<<NTOK / 256, 256>>>(tokens);
    embedding_stream_kernel<<<NEG * NBINS, 256>>>(tokens, W_e, W_p, out);
}

// round 7
// speedup vs baseline: 1.8636x; 1.2294x over previous
#include <cuda_runtime.h>
#include <cuda_bf16.h>

// out[b,s,e] = W_e[e, tokens[b,s]] + W_p[s,e]
// tokens: (2,2048) int32, W_e: (1024,32000) f32, W_p: (2048,1024) f32
// out: (2,2048,1024) f32
//
// Streaming formulation v3. W_e is read ONCE, fully sequentially (128MB at
// streaming BW beats gathering ~114MB of random 64B granules at ~4.4TB/s,
// the R1-R4 wall). Two launches:
//   1) binprep: single block bins the 4096 tokens by v>>8 into a packed CSR
//      list (tk<<8|vl), smem atomics + prefix sum. Replaces R6's two kernels.
//   2) stream: grid = 32 e-groups x 125 v-bins (bin fast). Each block
//      streams a (32 e-rows x 256 v) W_e tile into smem with aligned float4
//      loads, then emits 128B output rows only for its own bin's tokens.

#define B 2
#define S 2048
#define E 1024
#define V 32000
#define NTOK (B * S)          // 4096

#define V_TILE 256            // power of 2: bin = v>>8, rows 1024B (128B-aligned)
#define NBINS (V / V_TILE)    // 125
#define E_TILE 32
#define NEG (E / E_TILE)      // 32
#define SSTRIDE (V_TILE + 1)  // 257: odd -> distinct banks down a column

// Packed CSR: list[i] = (tk << 8) | vl, grouped by bin.
__device__ int g_bin_start[NBINS];
__device__ int g_bin_cnt[NBINS];
__device__ int g_list[NTOK];

__global__ __launch_bounds__(1024)
void binprep_kernel(const int* __restrict__ tokens) {
    __shared__ int cnt[NBINS];
    __shared__ int start[NBINS];
    __shared__ int cur[NBINS];
    int tid = threadIdx.x;

    if (tid < NBINS) { cnt[tid] = 0; }
    __syncthreads();

    int v[4], tk[4];
#pragma unroll
    for (int i = 0; i < 4; i++) {
        tk[i] = tid + 1024 * i;
        v[i]  = __ldg(&tokens[tk[i]]);
        atomicAdd(&cnt[v[i] >> 8], 1);
    }
    __syncthreads();

    if (tid == 0) {                       // 125-element exclusive prefix sum
        int acc = 0;
        for (int b = 0; b < NBINS; b++) { start[b] = acc; acc += cnt[b]; }
    }
    __syncthreads();
    if (tid < NBINS) {
        cur[tid] = start[tid];
        g_bin_start[tid] = start[tid];
        g_bin_cnt[tid]   = cnt[tid];
    }
    __syncthreads();

#pragma unroll
    for (int i = 0; i < 4; i++) {
        int bin = v[i] >> 8;
        int pos = atomicAdd(&cur[bin], 1);
        g_list[pos] = (tk[i] << 8) | (v[i] & 255);
    }
}

__global__ __launch_bounds__(256)
void embedding_stream_kernel(const float* __restrict__ W_e,
                             const float* __restrict__ W_p,
                             float* __restrict__ out) {
    __shared__ float tile[E_TILE * SSTRIDE];   // ~32.9KB

    int eg  = blockIdx.x / NBINS;              // e-group: slow axis
    int bin = blockIdx.x - eg * NBINS;         // v-bin:   fast axis (dense sweep)
    int tid = threadIdx.x;

    int v0 = bin * V_TILE;
    int e0 = eg * E_TILE;

    // ---- Phase 1: stream (32 x 256) tile, aligned float4 loads.
    //      2048 float4 / 256 threads = 8 per thread, all independent.
#pragma unroll
    for (int i = 0; i < 8; i++) {
        int idx = tid + 256 * i;
        int r = idx >> 6;                      // 0..31
        int c = idx & 63;                      // 0..63 (float4 within row)
        float4 val = __ldg(reinterpret_cast<const float4*>(
            W_e + (size_t)(e0 + r) * V + v0) + c);
        float* d = &tile[r * SSTRIDE + 4 * c];
        d[0] = val.x; d[1] = val.y; d[2] = val.z; d[3] = val.w;
    }
    __syncthreads();

    // ---- Phase 2: this bin's tokens only. 8 threads per token = one
    //      128B contiguous output row.
    int startb = g_bin_start[bin];
    int cnt    = g_bin_cnt[bin];
    int j      = tid & 7;                      // float4 slot in row
    for (int h = tid >> 3; h < cnt; h += 32) {
        int packed = g_list[startb + h];
        int tk = packed >> 8;
        int vl = packed & 255;
        int s  = tk & (S - 1);

        float4 p = __ldg(reinterpret_cast<const float4*>(
            W_p + (size_t)s * E + e0) + j);
        float4 r;
        r.x = tile[(4 * j + 0) * SSTRIDE + vl] + p.x;
        r.y = tile[(4 * j + 1) * SSTRIDE + vl] + p.y;
        r.z = tile[(4 * j + 2) * SSTRIDE + vl] + p.z;
        r.w = tile[(4 * j + 3) * SSTRIDE + vl] + p.w;
        __stcs(reinterpret_cast<float4*>(out + (size_t)tk * E + e0) + j, r);
    }
}

extern "C" void kernel_launch(void* const* d_in, const int* in_sizes, int n_in,
                              void* d_out, int out_size) {
    const int*   tokens = (const int*)d_in[0];
    const float* W_e    = (const float*)d_in[1];
    const float* W_p    = (const float*)d_in[2];
    float*       out    = (float*)d_out;

    binprep_kernel<<<1, 1024>>>(tokens);
    embedding_stream_kernel<<<NEG * NBINS, 256>>>(W_e, W_p, out);
}

// round 9
// speedup vs baseline: 2.1561x; 1.1569x over previous
#include <cuda_runtime.h>
#include <cuda_bf16.h>

// out[b,s,e] = W_e[e, tokens[b,s]] + W_p[s,e]
// tokens: (2,2048) int32, W_e: (1024,32000) f32, W_p: (2048,1024) f32
// out: (2,2048,1024) f32
//
// Streaming formulation v4b. W_e read ONCE, sequentially (128MB @ streaming
// BW beats gathering ~114MB of random 64B granules @ ~4.4TB/s = R1-R4 wall).
//   1) binprep: one block bins tokens by v>>8 into packed CSR (tk<<8|vl).
//      R8 bug fixed: all __syncthreads() now executed by ALL 1024 threads
//      (the R8 version had a barrier inside `if (tid<128)` -> UB -> crash).
//   2) stream: 32 e-groups x 125 v-bins (bin fast). Tile (32 x 256) -> smem
//      with SSTRIDE=260: rows 16B-aligned -> conflict-free STS.128 (R7's
//      stride-257 forced 4x STS.32 with 4-way conflicts = measured L1 wall).
//      __ldcs on the tile stream: single-use, evict-first.

#define B 2
#define S 2048
#define E 1024
#define V 32000
#define NTOK (B * S)          // 4096

#define V_TILE 256
#define NBINS (V / V_TILE)    // 125
#define E_TILE 32
#define NEG (E / E_TILE)      // 32
#define SSTRIDE 260           // row = 1040B: 16B-aligned -> STS.128, conflict-free

__device__ int g_bin_start[NBINS];
__device__ int g_bin_cnt[NBINS];
__device__ int g_list[NTOK];

__global__ __launch_bounds__(1024)
void binprep_kernel(const int* __restrict__ tokens) {
    __shared__ int cnt[128];           // 125 bins padded to 128
    __shared__ int cur[NBINS];
    __shared__ int warp_sum[4];
    int tid = threadIdx.x;

    if (tid < 128) cnt[tid] = 0;
    __syncthreads();

    // 4096 tokens / 1024 threads: one int4 load each.
    int4 tv = __ldg(reinterpret_cast<const int4*>(tokens) + tid);
    atomicAdd(&cnt[tv.x >> 8], 1);
    atomicAdd(&cnt[tv.y >> 8], 1);
    atomicAdd(&cnt[tv.z >> 8], 1);
    atomicAdd(&cnt[tv.w >> 8], 1);
    __syncthreads();

    // Block-wide exclusive scan over 128 slots. Warp-level work is barrier-
    // free; block barriers are executed by ALL threads.
    int x = 0, inc = 0;
    if (tid < 128) {
        int lane = tid & 31;
        x = cnt[tid];
        inc = x;
#pragma unroll
        for (int d = 1; d < 32; d <<= 1) {
            int y = __shfl_up_sync(0xffffffffu, inc, d);
            if (lane >= d) inc += y;
        }
        if (lane == 31) warp_sum[tid >> 5] = inc;
    }
    __syncthreads();                   // all 1024 threads
    if (tid < NBINS) {
        int w = tid >> 5;
        int base = 0;
#pragma unroll
        for (int k = 0; k < 4; k++) base += (k < w) ? warp_sum[k] : 0;
        int start = base + inc - x;    // exclusive prefix
        g_bin_start[tid] = start;
        g_bin_cnt[tid]   = x;
        cur[tid]         = start;
    }
    __syncthreads();                   // all 1024 threads

    int tk0 = tid * 4;
    int vv[4] = {tv.x, tv.y, tv.z, tv.w};
#pragma unroll
    for (int i = 0; i < 4; i++) {
        int v = vv[i];
        int pos = atomicAdd(&cur[v >> 8], 1);
        g_list[pos] = ((tk0 + i) << 8) | (v & 255);
    }
}

__global__ __launch_bounds__(256)
void embedding_stream_kernel(const float* __restrict__ W_e,
                             const float* __restrict__ W_p,
                             float* __restrict__ out) {
    __shared__ __align__(16) float tile[E_TILE * SSTRIDE];   // 33.3KB

    int eg  = blockIdx.x / NBINS;              // e-group: slow axis
    int bin = blockIdx.x - eg * NBINS;         // v-bin:   fast axis
    int tid = threadIdx.x;

    int v0 = bin * V_TILE;
    int e0 = eg * E_TILE;

    // ---- Phase 1: stream the (32 x 256) tile. 8 independent float4 loads
    //      per thread; aligned conflict-free STS.128 into smem.
#pragma unroll
    for (int i = 0; i < 8; i++) {
        int idx = tid + 256 * i;
        int r = idx >> 6;                      // 0..31
        int c = idx & 63;                      // 0..63
        float4 val = __ldcs(reinterpret_cast<const float4*>(
            W_e + (size_t)(e0 + r) * V + v0) + c);
        *reinterpret_cast<float4*>(&tile[r * SSTRIDE + 4 * c]) = val;
    }
    __syncthreads();

    // ---- Phase 2: this bin's tokens; 8 threads per token emit one 128B row.
    int startb = g_bin_start[bin];
    int cnt    = g_bin_cnt[bin];
    int j      = tid & 7;
    for (int h = tid >> 3; h < cnt; h += 32) {
        int packed = g_list[startb + h];
        int tk = packed >> 8;
        int vl = packed & 255;
        int s  = tk & (S - 1);

        float4 p = __ldg(reinterpret_cast<const float4*>(
            W_p + (size_t)s * E + e0) + j);
        float4 r;
        r.x = tile[(4 * j + 0) * SSTRIDE + vl] + p.x;
        r.y = tile[(4 * j + 1) * SSTRIDE + vl] + p.y;
        r.z = tile[(4 * j + 2) * SSTRIDE + vl] + p.z;
        r.w = tile[(4 * j + 3) * SSTRIDE + vl] + p.w;
        __stcs(reinterpret_cast<float4*>(out + (size_t)tk * E + e0) + j, r);
    }
}

extern "C" void kernel_launch(void* const* d_in, const int* in_sizes, int n_in,
                              void* d_out, int out_size) {
    const int*   tokens = (const int*)d_in[0];
    const float* W_e    = (const float*)d_in[1];
    const float* W_p    = (const float*)d_in[2];
    float*       out    = (float*)d_out;

    binprep_kernel<<<1, 1024>>>(tokens);
    embedding_stream_kernel<<<NEG * NBINS, 256>>>(W_e, W_p, out);
}

// round 11
// speedup vs baseline: 2.7333x; 1.2677x over previous
#include <cuda_runtime.h>
#include <cuda_bf16.h>

// out[b,s,e] = W_e[e, tokens[b,s]] + W_p[s,e]
// tokens: (2,2048) int32, W_e: (1024,32000) f32, W_p: (2048,1024) f32
// out: (2,2048,1024) f32
//
// Streaming v5 (R10 resubmit; R10 bench was an infra failure, no data).
// R9 showed the stream kernel latency-exposed (DRAM 52%, L1 36%, issue 14%:
// nothing saturated) because each short-lived block serialized
// load->barrier->epilogue. Fix:
//  - grid = 125 v-bins x 16 e-spans (2000 blocks); each block streams 4
//    subtiles (16 e-rows x 256 v) with cp.async.cg prefetch of tile t+1
//    overlapping the epilogue of tile t (loads never sit behind a barrier).
//  - per-block token scan (16 tests/thread) compacts this bin's hits into an
//    smem list, hidden under the tile-0 fetch. No separate binprep launch.

#define B 2
#define S 2048
#define E 1024
#define V 32000
#define NTOK (B * S)       // 4096

#define V_TILE 256
#define NBINS (V / V_TILE) // 125
#define ET 16              // e-rows per subtile
#define NSUB 4             // subtiles per block -> e-span 64
#define ESPANS 16          // 16 spans x 64 = 1024 = E
#define SSTRIDE 260        // 16B-aligned rows -> conflict-free STS/cp.async
#define CAP 2048           // hit-list capacity (fallback below if exceeded)

#define CP_ASYNC16(dst, src) \
    asm volatile("cp.async.cg.shared.global [%0], [%1], 16;" \
                 :: "r"(dst), "l"(src) : "memory")
#define CP_COMMIT() asm volatile("cp.async.commit_group;" ::: "memory")
#define CP_WAIT(n)  asm volatile("cp.async.wait_group %0;" :: "n"(n) : "memory")

__global__ __launch_bounds__(256)
void embed_kernel(const int* __restrict__ tokens,
                  const float* __restrict__ W_e,
                  const float* __restrict__ W_p,
                  float* __restrict__ out) {
    __shared__ int   list[CAP];                 // 8KB
    __shared__ __align__(16) float tile[2][ET * SSTRIDE];  // 33.3KB
    __shared__ int   s_cnt;

    int bin   = blockIdx.x % NBINS;
    int eh    = blockIdx.x / NBINS;             // 0..15
    int ebase = eh * (ET * NSUB);               // 64-row span
    int v0    = bin << 8;
    int tid   = threadIdx.x;

    if (tid == 0) s_cnt = 0;

    // ---- Prologue: async-issue tile 0 (overlaps the scan below).
#pragma unroll
    for (int i = 0; i < 4; i++) {
        int idx = tid + 256 * i;
        int r = idx >> 6, c = idx & 63;
        const float* src = W_e + (size_t)(ebase + r) * V + v0 + 4 * c;
        unsigned dst = (unsigned)__cvta_generic_to_shared(&tile[0][r * SSTRIDE + 4 * c]);
        CP_ASYNC16(dst, src);
    }
    CP_COMMIT();
    __syncthreads();                            // s_cnt=0 visible

    // ---- Scan: compact this bin's tokens (hidden under tile-0 fetch).
#pragma unroll
    for (int i = 0; i < 4; i++) {
        int4 tv = __ldg(reinterpret_cast<const int4*>(tokens) + tid + 256 * i);
        int tk0 = (tid + 256 * i) * 4;
        int vv[4] = {tv.x, tv.y, tv.z, tv.w};
#pragma unroll
        for (int k = 0; k < 4; k++) {
            if ((vv[k] >> 8) == bin) {
                int pos = atomicAdd(&s_cnt, 1);
                if (pos < CAP) list[pos] = ((tk0 + k) << 8) | (vv[k] & 255);
            }
        }
    }
    __syncthreads();
    int total = s_cnt;

    if (total <= CAP) {
        // ---- Fast path: 4-subtile double-buffered pipeline.
        int j = tid & 3;                        // float4 slot (16 floats/row)
        int hb = tid >> 2;                      // 64 tokens per pass
#pragma unroll
        for (int t = 0; t < NSUB; t++) {
            if (t < NSUB - 1) {                 // prefetch t+1
#pragma unroll
                for (int i = 0; i < 4; i++) {
                    int idx = tid + 256 * i;
                    int r = idx >> 6, c = idx & 63;
                    const float* src = W_e + (size_t)(ebase + (t + 1) * ET + r) * V + v0 + 4 * c;
                    unsigned dst = (unsigned)__cvta_generic_to_shared(
                        &tile[(t + 1) & 1][r * SSTRIDE + 4 * c]);
                    CP_ASYNC16(dst, src);
                }
                CP_COMMIT();
                CP_WAIT(1);                     // tile t complete
            } else {
                CP_WAIT(0);
            }
            __syncthreads();

            const float* tl = tile[t & 1];
            int e0 = ebase + t * ET;
            for (int h = hb; h < total; h += 64) {
                int packed = list[h];
                int tk = packed >> 8;
                int vl = packed & 255;
                int s  = tk & (S - 1);
                float4 p = __ldg(reinterpret_cast<const float4*>(
                    W_p + (size_t)s * E + e0) + j);
                float4 r;
                r.x = tl[(4 * j + 0) * SSTRIDE + vl] + p.x;
                r.y = tl[(4 * j + 1) * SSTRIDE + vl] + p.y;
                r.z = tl[(4 * j + 2) * SSTRIDE + vl] + p.z;
                r.w = tl[(4 * j + 3) * SSTRIDE + vl] + p.w;
                __stcs(reinterpret_cast<float4*>(out + (size_t)tk * E + e0) + j, r);
            }
            __syncthreads();                    // buf t reusable at t+2 issue
        }
    } else {
        // ---- Fallback (pathological token skew; never hit by this input).
        CP_WAIT(0);
        __syncthreads();
        for (int t = 0; t < NSUB; t++) {
#pragma unroll
            for (int i = 0; i < 4; i++) {
                int idx = tid + 256 * i;
                int r = idx >> 6, c = idx & 63;
                float4 val = __ldg(reinterpret_cast<const float4*>(
                    W_e + (size_t)(ebase + t * ET + r) * V + v0) + c);
                *reinterpret_cast<float4*>(&tile[0][r * SSTRIDE + 4 * c]) = val;
            }
            __syncthreads();
            int e0 = ebase + t * ET;
            for (int idx = tid; idx < NTOK; idx += 256) {
                int v = __ldg(&tokens[idx]);
                if ((v >> 8) == bin) {
                    int vl = v & 255;
                    int s  = idx & (S - 1);
                    for (int rr = 0; rr < ET; rr++)
                        out[(size_t)idx * E + e0 + rr] =
                            tile[0][rr * SSTRIDE + vl] + W_p[(size_t)s * E + e0 + rr];
                }
            }
            __syncthreads();
        }
    }
}

extern "C" void kernel_launch(void* const* d_in, const int* in_sizes, int n_in,
                              void* d_out, int out_size) {
    const int*   tokens = (const int*)d_in[0];
    const float* W_e    = (const float*)d_in[1];
    const float* W_p    = (const float*)d_in[2];
    float*       out    = (float*)d_out;

    embed_kernel<<<NBINS * ESPANS, 256>>>(tokens, W_e, W_p, out);
}